// round 14
// baseline (speedup 1.0000x reference)
#include <cuda_runtime.h>
#include <math.h>
#include <stdint.h>

#define DIMC 256
#define QKD  256
#define NHEADS 8
#define NTOPK 4
#define HID  1024
#define NB   8
#define HW   64
#define NTOK (NB*HW*HW)      /* 32768 tokens */
#define P2   256             /* windows per image */
#define W2   16              /* tokens per window */
#define ATT_SCALE 0.0625f    /* 256^-0.5 */

/* ------------ scratch (device globals; no allocations allowed) ------------ */
__device__ float g_xt [(size_t)NTOK*DIMC];
__device__ float g_q  [(size_t)NTOK*QKD];
__device__ float g_kv [(size_t)NTOK*(QKD+DIMC)];
__device__ float g_qwin[NB*P2*QKD];
__device__ float g_kwin[NB*P2*QKD];
__device__ int   g_ridx[NB*P2*NTOPK];
__device__ float g_attn[(size_t)NTOK*DIMC];
__device__ float g_x1 [(size_t)NTOK*DIMC];
__device__ float g_h1 [(size_t)NTOK*HID];
__device__ float g_h2 [(size_t)NTOK*DIMC];

/* bf16 hi/lo decomposed GEMM operands (uint16 bit-patterns) */
__device__ uint16_t g_xt_h [(size_t)NTOK*DIMC];
__device__ uint16_t g_xt_l [(size_t)NTOK*DIMC];
__device__ uint16_t g_x1_h [(size_t)NTOK*DIMC];
__device__ uint16_t g_x1_l [(size_t)NTOK*DIMC];
__device__ uint16_t g_h1c_h[(size_t)NTOK*HID];
__device__ uint16_t g_h1c_l[(size_t)NTOK*HID];
__device__ uint16_t g_wq_h [QKD*DIMC],        g_wq_l [QKD*DIMC];
__device__ uint16_t g_wkv_h[(QKD+DIMC)*DIMC], g_wkv_l[(QKD+DIMC)*DIMC];
__device__ uint16_t g_wf1_h[HID*DIMC],        g_wf1_l[HID*DIMC];
__device__ uint16_t g_wf2_h[DIMC*HID],        g_wf2_l[DIMC*HID];

/* ========================= helpers ======================================== */
__device__ __forceinline__ uint32_t smem_u32(const void* p) {
    uint32_t a;
    asm("{ .reg .u64 t; cvta.to.shared.u64 t, %1; cvt.u32.u64 %0, t; }" : "=r"(a) : "l"(p));
    return a;
}
__device__ __forceinline__ uint16_t bf16h(float x) {
    uint16_t u; asm("cvt.rn.bf16.f32 %0, %1;" : "=h"(u) : "f"(x)); return u;
}
__device__ __forceinline__ float bf16f(uint16_t u) {
    return __uint_as_float(((uint32_t)u) << 16);
}
__device__ __forceinline__ void bf16dec(float x, uint16_t& h, uint16_t& l) {
    h = bf16h(x);
    l = bf16h(x - bf16f(h));
}
__device__ __forceinline__ void mma_bf16(float* c, const uint32_t* a, const uint32_t* b) {
    asm volatile("mma.sync.aligned.m16n8k16.row.col.f32.bf16.bf16.f32 "
        "{%0,%1,%2,%3}, {%4,%5,%6,%7}, {%8,%9}, {%0,%1,%2,%3};"
        : "+f"(c[0]), "+f"(c[1]), "+f"(c[2]), "+f"(c[3])
        : "r"(a[0]), "r"(a[1]), "r"(a[2]), "r"(a[3]), "r"(b[0]), "r"(b[1]));
}
__device__ __forceinline__ void ldsm4(uint32_t* r, uint32_t addr) {
    asm volatile("ldmatrix.sync.aligned.m8n8.x4.shared.b16 {%0,%1,%2,%3}, [%4];"
        : "=r"(r[0]), "=r"(r[1]), "=r"(r[2]), "=r"(r[3]) : "r"(addr));
}
#define CP_ASYNC16(sa, ga) \
    asm volatile("cp.async.cg.shared.global [%0], [%1], 16;" :: "r"(sa), "l"(ga) : "memory")
#define CP_COMMIT() asm volatile("cp.async.commit_group;" ::: "memory")
#define CP_WAIT(n)  asm volatile("cp.async.wait_group %0;" :: "n"(n) : "memory")

/* smem: per stage 4 components (Ah, Al, Wh, Wl), each 128 rows x 32 bf16,  */
/* row stride 80 bytes -> ldmatrix 8-row footprint conflict-free            */
#define BSTRIDE 80
#define COMP_BYTES (128*BSTRIDE)      /* 10240 */
#define STAGE_BYTES (4*COMP_BYTES)    /* 40960 */
#define GEMM_SMEM (2*STAGE_BYTES)     /* 81920 */

/* == bf16x3 GEMM, hi/lo precomputed, 512 thr / 16 warps (4x4 warp grid) === */
__global__ __launch_bounds__(512)
void k_gemm_bf3(const uint16_t* __restrict__ Ah, const uint16_t* __restrict__ Al,
                const uint16_t* __restrict__ Wh, const uint16_t* __restrict__ Wl,
                const float* __restrict__ gg, const float* __restrict__ bb,
                float* __restrict__ C, int M, int N, int K)
{
    extern __shared__ char smraw[];
    const uint32_t smbase = smem_u32(smraw);
    const int tid = threadIdx.x;
    const int wid = tid >> 5, lane = tid & 31;
    const int g = lane >> 2, t = lane & 3;
    const int wm = wid >> 2, wn = wid & 3;     /* warp grid 4 x 4, tile 32x32 */
    const int bm = blockIdx.y * 128, bn = blockIdx.x * 128;

    /* loader mapping: 512 threads, each 1 cp.async per component */
    const int lrow = tid >> 2, lseg = tid & 3;
    /* ldmatrix per-lane address components */
    const int l7 = lane & 7;
    const int a_row = l7 + ((lane >> 3) & 1) * 8;
    const int a_kb  = (lane >> 4) * 16;
    const int b_col = l7 + (lane >> 4) * 8;
    const int b_kb  = ((lane >> 3) & 1) * 16;

    float c[2][4][4];
    #pragma unroll
    for (int i = 0; i < 2; i++)
        #pragma unroll
        for (int j = 0; j < 4; j++)
            #pragma unroll
            for (int k = 0; k < 4; k++) c[i][j][k] = 0.f;

    const int nch = K >> 5;

    /* prefetch chunk 0 */
    {
        uint32_t st = smbase;
        #pragma unroll
        for (int comp = 0; comp < 4; comp++) {
            const uint16_t* src;
            int base;
            if (comp == 0)      { src = Ah; base = bm; }
            else if (comp == 1) { src = Al; base = bm; }
            else if (comp == 2) { src = Wh; base = bn; }
            else                { src = Wl; base = bn; }
            CP_ASYNC16(st + comp * COMP_BYTES + lrow * BSTRIDE + lseg * 16,
                       src + (size_t)(base + lrow) * K + lseg * 8);
        }
        CP_COMMIT();
    }

    for (int ch = 0; ch < nch; ch++) {
        if (ch + 1 < nch) {
            uint32_t st = smbase + ((ch + 1) & 1) * STAGE_BYTES;
            int kc = (ch + 1) << 5;
            #pragma unroll
            for (int comp = 0; comp < 4; comp++) {
                const uint16_t* src;
                int base;
                if (comp == 0)      { src = Ah; base = bm; }
                else if (comp == 1) { src = Al; base = bm; }
                else if (comp == 2) { src = Wh; base = bn; }
                else                { src = Wl; base = bn; }
                CP_ASYNC16(st + comp * COMP_BYTES + lrow * BSTRIDE + lseg * 16,
                           src + (size_t)(base + lrow) * K + kc + lseg * 8);
            }
            CP_COMMIT();
            CP_WAIT(1);
        } else {
            CP_WAIT(0);
        }
        __syncthreads();

        uint32_t sAh = smbase + (ch & 1) * STAGE_BYTES;
        uint32_t sWh = sAh + 2 * COMP_BYTES;

        #pragma unroll
        for (int ks = 0; ks < 2; ks++) {
            uint32_t ah[2][4], al[2][4], bh[2][4], bl[2][4];
            #pragma unroll
            for (int mt = 0; mt < 2; mt++) {
                uint32_t base = sAh + (uint32_t)(wm * 32 + mt * 16 + a_row) * BSTRIDE
                              + a_kb + ks * 32;
                ldsm4(ah[mt], base);
                ldsm4(al[mt], base + COMP_BYTES);
            }
            #pragma unroll
            for (int pr = 0; pr < 2; pr++) {
                uint32_t base = sWh + (uint32_t)(wn * 32 + pr * 16 + b_col) * BSTRIDE
                              + b_kb + ks * 32;
                ldsm4(bh[pr], base);
                ldsm4(bl[pr], base + COMP_BYTES);
            }
            #pragma unroll
            for (int mt = 0; mt < 2; mt++)
                #pragma unroll
                for (int nt = 0; nt < 4; nt++) {
                    const uint32_t* BH = &bh[nt >> 1][(nt & 1) * 2];
                    const uint32_t* BL = &bl[nt >> 1][(nt & 1) * 2];
                    mma_bf16(c[mt][nt], ah[mt], BL);
                    mma_bf16(c[mt][nt], al[mt], BH);
                    mma_bf16(c[mt][nt], ah[mt], BH);
                }
        }
        __syncthreads();
    }

    /* ---- epilogue: scale * acc + bias ---- */
    #pragma unroll
    for (int mt = 0; mt < 2; mt++) {
        int r0 = bm + wm * 32 + mt * 16 + g;
        #pragma unroll
        for (int nt = 0; nt < 4; nt++) {
            int col = bn + wn * 32 + nt * 8 + t * 2;
            float2 gv = *(const float2*)(gg + col);
            float2 bv = *(const float2*)(bb + col);
            float2 o0, o1;
            o0.x = c[mt][nt][0] * gv.x + bv.x;
            o0.y = c[mt][nt][1] * gv.y + bv.y;
            o1.x = c[mt][nt][2] * gv.x + bv.x;
            o1.y = c[mt][nt][3] * gv.y + bv.y;
            *(float2*)(C + (size_t)r0 * N + col) = o0;
            *(float2*)(C + (size_t)(r0 + 8) * N + col) = o1;
        }
    }
}

/* --------- merged hi/lo decompose of all 4 weight tensors ----------------- */
#define NW1 (QKD*DIMC)                    /*  65536 */
#define NW2 (NW1 + (QKD+DIMC)*DIMC)       /* 196608 */
#define NW3 (NW2 + HID*DIMC)              /* 458752 */
#define NW4 (NW3 + DIMC*HID)              /* 720896 */
__global__ void k_dec_all(const float* __restrict__ wq, const float* __restrict__ wkv,
                          const float* __restrict__ wf1, const float* __restrict__ wf2) {
    int i = blockIdx.x * 256 + threadIdx.x;
    const float* s; uint16_t* h; uint16_t* l; int o;
    if (i < NW1)      { s = wq;  h = g_wq_h;  l = g_wq_l;  o = i; }
    else if (i < NW2) { s = wkv; h = g_wkv_h; l = g_wkv_l; o = i - NW1; }
    else if (i < NW3) { s = wf1; h = g_wf1_h; l = g_wf1_l; o = i - NW2; }
    else if (i < NW4) { s = wf2; h = g_wf2_h; l = g_wf2_l; o = i - NW3; }
    else return;
    uint16_t hh, ll;
    bf16dec(s[o], hh, ll);
    h[o] = hh; l[o] = ll;
}

/* ------------------- NCHW -> token-layout transpose (+dec) ---------------- */
__global__ void k_transpose_in(const float* __restrict__ x) {
    __shared__ float tile[32][33];
    int ny = blockIdx.z;
    int n = ny >> 6, y = ny & 63;
    int c0 = blockIdx.y * 32;
    int x0 = blockIdx.x * 32;
    int tx = threadIdx.x, ty = threadIdx.y;
    const float* src = x + (((size_t)n*DIMC + c0)*HW + y)*HW + x0;
    for (int i = ty; i < 32; i += 8)
        tile[i][tx] = src[(size_t)i*HW*HW + tx];
    __syncthreads();
    size_t tb = (size_t)(n*4096 + y*64 + x0);
    for (int i = ty; i < 32; i += 8) {
        float v = tile[tx][i];
        size_t o = (tb + i)*DIMC + c0 + tx;
        g_xt[o] = v;
        uint16_t hh, ll; bf16dec(v, hh, ll);
        g_xt_h[o] = hh; g_xt_l[o] = ll;
    }
}

/* ---------------- per-window mean of q and of k (kv[:256]) ----------------- */
__global__ void k_winmeans() {
    int np = blockIdx.x;
    int n = np >> 8, p = np & 255;
    int o = threadIdx.x;
    int yb = (p >> 4) * 4, xb = (p & 15) * 4;
    float qs = 0.f, ks = 0.f;
    #pragma unroll
    for (int tok = 0; tok < 16; tok++) {
        size_t t = (size_t)(n*4096 + (yb + (tok>>2))*64 + xb + (tok&3));
        qs += g_q[t*QKD + o];
        ks += g_kv[t*512 + o];
    }
    g_qwin[np*256 + o] = qs * (1.f/16.f);
    g_kwin[np*256 + o] = ks * (1.f/16.f);
}

/* ---------------- routing: 256 logits per window -> top-4 indices ---------- */
__global__ void k_route() {
    __shared__ float qrow[256];
    __shared__ float logit[256];
    __shared__ float rv[256];
    __shared__ int   ri[256];
    __shared__ int   chosen[NTOPK];
    int np = blockIdx.x;
    int n = np >> 8;
    int tid = threadIdx.x;
    qrow[tid] = g_qwin[np*256 + tid] * ATT_SCALE;
    __syncthreads();
    const float* kr = &g_kwin[(size_t)n*256*256 + (size_t)tid*256];
    float a = 0.f;
    #pragma unroll 8
    for (int c = 0; c < 256; c++) a += qrow[c] * kr[c];
    logit[tid] = a;
    __syncthreads();
    for (int sel = 0; sel < NTOPK; sel++) {
        bool masked = false;
        for (int s = 0; s < sel; s++) if (chosen[s] == tid) masked = true;
        rv[tid] = masked ? -INFINITY : logit[tid];
        ri[tid] = tid;
        __syncthreads();
        for (int s = 128; s > 0; s >>= 1) {
            if (tid < s) {
                float v2 = rv[tid+s]; int i2 = ri[tid+s];
                if (v2 > rv[tid] || (v2 == rv[tid] && i2 < ri[tid])) { rv[tid] = v2; ri[tid] = i2; }
            }
            __syncthreads();
        }
        if (tid == 0) { chosen[sel] = ri[0]; g_ridx[np*4 + sel] = ri[0]; }
        __syncthreads();
    }
}

/* --------- gathered attention: block per window, 2 heads per pass ---------- */
__launch_bounds__(256)
__global__ void k_attn() {
    __shared__ float q_s[16][65];
    __shared__ float k_s[64][65];
    __shared__ float v_s[64][65];
    __shared__ int   sridx[4];
    __shared__ int   stok[64];
    int np = blockIdx.x;
    int n = np >> 8, p = np & 255;
    int tid = threadIdx.x;
    if (tid < 4) sridx[tid] = g_ridx[np*4 + tid];
    __syncthreads();
    if (tid < 64) {
        int sel = tid >> 4, tok = tid & 15;
        int ps = sridx[sel];
        stok[tid] = n*4096 + ((ps>>4)*4 + (tok>>2))*64 + (ps&15)*4 + (tok&3);
    }
    __syncthreads();
    int qtok_base = n*4096 + (p>>4)*4*64 + (p&15)*4;
    int warp = tid >> 5, lane = tid & 31;
    for (int g2 = 0; g2 < 4; g2++) {
        int c0 = g2 * 64;
        for (int i = tid; i < 16*64; i += 256) {
            int tok = i >> 6, cc = i & 63;
            size_t t = (size_t)(qtok_base + (tok>>2)*64 + (tok&3));
            q_s[tok][cc] = g_q[t*256 + c0 + cc];
        }
        for (int i = tid; i < 64*64; i += 256) {
            int kt = i >> 6, cc = i & 63;
            size_t t = (size_t)stok[kt];
            k_s[kt][cc] = g_kv[t*512 + c0 + cc];
            v_s[kt][cc] = g_kv[t*512 + 256 + c0 + cc];
        }
        __syncthreads();
        int hoff  = (warp >> 2) * 32;
        int qi    = (warp & 3) * 4 + (lane >> 3);
        int kbase = (lane & 7) * 8;
        float qreg[32];
        #pragma unroll
        for (int c = 0; c < 32; c++) qreg[c] = q_s[qi][hoff + c] * ATT_SCALE;
        float sc[8];
        #pragma unroll
        for (int j = 0; j < 8; j++) {
            float a = 0.f;
            #pragma unroll
            for (int c = 0; c < 32; c++) a += qreg[c] * k_s[kbase + j][hoff + c];
            sc[j] = a;
        }
        float mx = sc[0];
        #pragma unroll
        for (int j = 1; j < 8; j++) mx = fmaxf(mx, sc[j]);
        #pragma unroll
        for (int s = 1; s < 8; s <<= 1) mx = fmaxf(mx, __shfl_xor_sync(0xffffffffu, mx, s));
        float sum = 0.f;
        #pragma unroll
        for (int j = 0; j < 8; j++) { sc[j] = expf(sc[j] - mx); sum += sc[j]; }
        #pragma unroll
        for (int s = 1; s < 8; s <<= 1) sum += __shfl_xor_sync(0xffffffffu, sum, s);
        float inv = 1.f / sum;
        float out[32];
        #pragma unroll
        for (int c = 0; c < 32; c++) out[c] = 0.f;
        #pragma unroll
        for (int j = 0; j < 8; j++) {
            float pj = sc[j] * inv;
            #pragma unroll
            for (int c = 0; c < 32; c++) out[c] += pj * v_s[kbase + j][hoff + c];
        }
        #pragma unroll
        for (int s = 1; s < 8; s <<= 1)
            #pragma unroll
            for (int c = 0; c < 32; c++) out[c] += __shfl_xor_sync(0xffffffffu, out[c], s);
        if ((lane & 7) == 0) {
            size_t t = (size_t)(qtok_base + (qi>>2)*64 + (qi&3));
            float* dst = &g_attn[t*256 + c0 + hoff];
            #pragma unroll
            for (int c = 0; c < 32; c++) dst[c] = out[c];
        }
        __syncthreads();
    }
}

/* ------- LEPE 5x5 dw on V + residual: x1 = x + attn + lepe (+dec) --------- */
__global__ void k_lepe_add(const float* __restrict__ w_lepe, const float* __restrict__ b_lepe) {
    size_t idx = (size_t)blockIdx.x*256 + threadIdx.x;
    int c = (int)(idx & 255);
    int t = (int)(idx >> 8);
    int n = t >> 12, rem = t & 4095, y = rem >> 6, x = rem & 63;
    float acc = b_lepe[c];
    #pragma unroll
    for (int dy = 0; dy < 5; dy++) {
        int yy = y + dy - 2;
        if (yy < 0 || yy >= 64) continue;
        #pragma unroll
        for (int dx = 0; dx < 5; dx++) {
            int xx = x + dx - 2;
            if (xx < 0 || xx >= 64) continue;
            size_t tt = (size_t)(n*4096 + yy*64 + xx);
            acc += g_kv[tt*512 + 256 + c] * w_lepe[c*25 + dy*5 + dx];
        }
    }
    float r = g_xt[idx] + g_attn[idx] + acc;
    g_x1[idx] = r;
    uint16_t hh, ll; bf16dec(r, hh, ll);
    g_x1_h[idx] = hh; g_x1_l[idx] = ll;
}

/* ------- 3x3 depthwise on h1 (1024 ch) + bias + ReLU -> hi/lo bf16 -------- */
__global__ void k_dw3relu(const float* __restrict__ w_dw, const float* __restrict__ b_dw) {
    size_t idx = (size_t)blockIdx.x*256 + threadIdx.x;
    int ch = (int)(idx & 1023);
    int t = (int)(idx >> 10);
    int n = t >> 12, rem = t & 4095, y = rem >> 6, x = rem & 63;
    float acc = b_dw[ch];
    #pragma unroll
    for (int dy = 0; dy < 3; dy++) {
        int yy = y + dy - 1;
        if (yy < 0 || yy >= 64) continue;
        #pragma unroll
        for (int dx = 0; dx < 3; dx++) {
            int xx = x + dx - 1;
            if (xx < 0 || xx >= 64) continue;
            size_t tt = (size_t)(n*4096 + yy*64 + xx);
            acc += g_h1[tt*1024 + ch] * w_dw[ch*9 + dy*3 + dx];
        }
    }
    float v = fmaxf(acc, 0.f);
    uint16_t hh, ll; bf16dec(v, hh, ll);
    g_h1c_h[idx] = hh; g_h1c_l[idx] = ll;
}

/* --------- final residual + token-layout -> NCHW transpose ----------------- */
__global__ void k_final(float* __restrict__ out) {
    __shared__ float tile[32][33];
    int ny = blockIdx.z;
    int n = ny >> 6, y = ny & 63;
    int c0 = blockIdx.y * 32, x0 = blockIdx.x * 32;
    int tx = threadIdx.x, ty = threadIdx.y;
    size_t tb = (size_t)(n*4096 + y*64 + x0);
    for (int i = ty; i < 32; i += 8) {
        size_t o = (tb + i)*256 + c0 + tx;
        tile[i][tx] = g_x1[o] + g_h2[o];
    }
    __syncthreads();
    float* dst = out + (((size_t)n*DIMC + c0)*HW + y)*HW + x0;
    for (int i = ty; i < 32; i += 8)
        dst[(size_t)i*HW*HW + tx] = tile[tx][i];
}

/* --------------------------------------------------------------------------- */
extern "C" void kernel_launch(void* const* d_in, const int* in_sizes, int n_in,
                              void* d_out, int out_size)
{
    const float* x      = (const float*)d_in[0];
    const float* wq     = (const float*)d_in[1];
    const float* gq     = (const float*)d_in[2];
    const float* bq     = (const float*)d_in[3];
    const float* wkv    = (const float*)d_in[4];
    const float* gkv    = (const float*)d_in[5];
    const float* bkv    = (const float*)d_in[6];
    const float* w_lepe = (const float*)d_in[7];
    const float* b_lepe = (const float*)d_in[8];
    const float* w_fc1  = (const float*)d_in[9];
    const float* g_fc1  = (const float*)d_in[10];
    const float* b_fc1  = (const float*)d_in[11];
    const float* w_dw   = (const float*)d_in[12];
    const float* b_dw   = (const float*)d_in[13];
    const float* w_fc2  = (const float*)d_in[14];
    const float* g_fc2  = (const float*)d_in[15];
    const float* b_fc2  = (const float*)d_in[16];
    float* out = (float*)d_out;

    float *q, *kv, *h1, *h2;
    uint16_t *xth, *xtl, *x1h, *x1l, *h1ch, *h1cl;
    uint16_t *wqh, *wql, *wkvh, *wkvl, *wf1h, *wf1l, *wf2h, *wf2l;
    cudaGetSymbolAddress((void**)&q,    g_q);
    cudaGetSymbolAddress((void**)&kv,   g_kv);
    cudaGetSymbolAddress((void**)&h1,   g_h1);
    cudaGetSymbolAddress((void**)&h2,   g_h2);
    cudaGetSymbolAddress((void**)&xth,  g_xt_h);
    cudaGetSymbolAddress((void**)&xtl,  g_xt_l);
    cudaGetSymbolAddress((void**)&x1h,  g_x1_h);
    cudaGetSymbolAddress((void**)&x1l,  g_x1_l);
    cudaGetSymbolAddress((void**)&h1ch, g_h1c_h);
    cudaGetSymbolAddress((void**)&h1cl, g_h1c_l);
    cudaGetSymbolAddress((void**)&wqh,  g_wq_h);
    cudaGetSymbolAddress((void**)&wql,  g_wq_l);
    cudaGetSymbolAddress((void**)&wkvh, g_wkv_h);
    cudaGetSymbolAddress((void**)&wkvl, g_wkv_l);
    cudaGetSymbolAddress((void**)&wf1h, g_wf1_h);
    cudaGetSymbolAddress((void**)&wf1l, g_wf1_l);
    cudaGetSymbolAddress((void**)&wf2h, g_wf2_h);
    cudaGetSymbolAddress((void**)&wf2l, g_wf2_l);

    cudaFuncSetAttribute(k_gemm_bf3, cudaFuncAttributeMaxDynamicSharedMemorySize, GEMM_SMEM);

    dim3 tblk(32, 8);
    dim3 tgrid(2, 8, NB*HW);

    /* launch 0: merged weight decomposition */
    k_dec_all<<<(NW4 + 255)/256, 256>>>(wq, wkv, w_fc1, w_fc2);
    /* launch 1 */
    k_transpose_in<<<tgrid, tblk>>>(x);
    /* launches 2-3: q / kv projections (bf16x3 tensor cores) */
    k_gemm_bf3<<<dim3(QKD/128, NTOK/128), 512, GEMM_SMEM>>>(xth, xtl, wqh,  wql,  gq,  bq,  q,  NTOK, QKD, DIMC);
    k_gemm_bf3<<<dim3((QKD+DIMC)/128, NTOK/128), 512, GEMM_SMEM>>>(xth, xtl, wkvh, wkvl, gkv, bkv, kv, NTOK, QKD+DIMC, DIMC);

    k_winmeans<<<NB*P2, 256>>>();
    k_route<<<NB*P2, 256>>>();
    k_attn<<<NB*P2, 256>>>();
    k_lepe_add<<<NTOK, 256>>>(w_lepe, b_lepe);

    /* MLP */
    k_gemm_bf3<<<dim3(HID/128, NTOK/128), 512, GEMM_SMEM>>>(x1h, x1l, wf1h, wf1l, g_fc1, b_fc1, h1, NTOK, HID, DIMC);
    k_dw3relu<<<NTOK*HID/256, 256>>>(w_dw, b_dw);
    k_gemm_bf3<<<dim3(DIMC/128, NTOK/128), 512, GEMM_SMEM>>>(h1ch, h1cl, wf2h, wf2l, g_fc2, b_fc2, h2, NTOK, DIMC, HID);

    k_final<<<tgrid, tblk>>>(out);
}

// round 15
// speedup vs baseline: 1.0816x; 1.0816x over previous
#include <cuda_runtime.h>
#include <math.h>
#include <stdint.h>

#define DIMC 256
#define QKD  256
#define NHEADS 8
#define NTOPK 4
#define HID  1024
#define NB   8
#define HW   64
#define NTOK (NB*HW*HW)      /* 32768 tokens */
#define P2   256             /* windows per image */
#define W2   16              /* tokens per window */
#define ATT_SCALE 0.0625f    /* 256^-0.5 */

/* ------------ scratch (device globals; no allocations allowed) ------------ */
__device__ float g_xt [(size_t)NTOK*DIMC];
__device__ float g_q  [(size_t)NTOK*QKD];
__device__ float g_kv [(size_t)NTOK*(QKD+DIMC)];
__device__ float g_qwin[NB*P2*QKD];
__device__ float g_kwin[NB*P2*QKD];
__device__ int   g_ridx[NB*P2*NTOPK];
__device__ float g_attn[(size_t)NTOK*DIMC];
__device__ float g_x1 [(size_t)NTOK*DIMC];
__device__ float g_h1 [(size_t)NTOK*HID];
__device__ float g_h2 [(size_t)NTOK*DIMC];

/* bf16 hi/lo decomposed GEMM operands (uint16 bit-patterns) */
__device__ uint16_t g_xt_h [(size_t)NTOK*DIMC];
__device__ uint16_t g_xt_l [(size_t)NTOK*DIMC];
__device__ uint16_t g_x1_h [(size_t)NTOK*DIMC];
__device__ uint16_t g_x1_l [(size_t)NTOK*DIMC];
__device__ uint16_t g_h1c_h[(size_t)NTOK*HID];
__device__ uint16_t g_h1c_l[(size_t)NTOK*HID];
__device__ uint16_t g_wq_h [QKD*DIMC],        g_wq_l [QKD*DIMC];
__device__ uint16_t g_wkv_h[(QKD+DIMC)*DIMC], g_wkv_l[(QKD+DIMC)*DIMC];
__device__ uint16_t g_wf1_h[HID*DIMC],        g_wf1_l[HID*DIMC];
__device__ uint16_t g_wf2_h[DIMC*HID],        g_wf2_l[DIMC*HID];

/* ========================= helpers ======================================== */
__device__ __forceinline__ uint32_t smem_u32(const void* p) {
    uint32_t a;
    asm("{ .reg .u64 t; cvta.to.shared.u64 t, %1; cvt.u32.u64 %0, t; }" : "=r"(a) : "l"(p));
    return a;
}
__device__ __forceinline__ uint16_t bf16h(float x) {
    uint16_t u; asm("cvt.rn.bf16.f32 %0, %1;" : "=h"(u) : "f"(x)); return u;
}
__device__ __forceinline__ float bf16f(uint16_t u) {
    return __uint_as_float(((uint32_t)u) << 16);
}
__device__ __forceinline__ void bf16dec(float x, uint16_t& h, uint16_t& l) {
    h = bf16h(x);
    l = bf16h(x - bf16f(h));
}
__device__ __forceinline__ void mma_bf16(float* c, const uint32_t* a, const uint32_t* b) {
    asm volatile("mma.sync.aligned.m16n8k16.row.col.f32.bf16.bf16.f32 "
        "{%0,%1,%2,%3}, {%4,%5,%6,%7}, {%8,%9}, {%0,%1,%2,%3};"
        : "+f"(c[0]), "+f"(c[1]), "+f"(c[2]), "+f"(c[3])
        : "r"(a[0]), "r"(a[1]), "r"(a[2]), "r"(a[3]), "r"(b[0]), "r"(b[1]));
}
__device__ __forceinline__ void ldsm4(uint32_t* r, uint32_t addr) {
    asm volatile("ldmatrix.sync.aligned.m8n8.x4.shared.b16 {%0,%1,%2,%3}, [%4];"
        : "=r"(r[0]), "=r"(r[1]), "=r"(r[2]), "=r"(r[3]) : "r"(addr));
}
#define CP_ASYNC16(sa, ga) \
    asm volatile("cp.async.cg.shared.global [%0], [%1], 16;" :: "r"(sa), "l"(ga) : "memory")
#define CP_COMMIT() asm volatile("cp.async.commit_group;" ::: "memory")
#define CP_WAIT(n)  asm volatile("cp.async.wait_group %0;" :: "n"(n) : "memory")

/* smem: per stage 4 components (Ah, Al, Wh, Wl), each 128 rows x 32 bf16,  */
/* row stride 80 bytes -> ldmatrix 8-row footprint conflict-free            */
#define BSTRIDE 80
#define COMP_BYTES (128*BSTRIDE)      /* 10240 */
#define STAGE_BYTES (4*COMP_BYTES)    /* 40960 */
#define GEMM_SMEM (2*STAGE_BYTES)     /* 81920 */

/* ====== bf16x3 GEMM, hi/lo precomputed: C = (A @ W^T) * g + b ============ */
__global__ __launch_bounds__(256)
void k_gemm_bf3(const uint16_t* __restrict__ Ah, const uint16_t* __restrict__ Al,
                const uint16_t* __restrict__ Wh, const uint16_t* __restrict__ Wl,
                const float* __restrict__ gg, const float* __restrict__ bb,
                float* __restrict__ C, int M, int N, int K)
{
    extern __shared__ char smraw[];
    const uint32_t smbase = smem_u32(smraw);
    const int tid = threadIdx.x;
    const int wid = tid >> 5, lane = tid & 31;
    const int g = lane >> 2, t = lane & 3;
    const int wm = wid >> 2, wn = wid & 3;     /* warp grid 2 x 4 */
    const int bm = blockIdx.y * 128, bn = blockIdx.x * 128;

    const int lrow = tid >> 2, lseg = tid & 3;
    const int l7 = lane & 7;
    const int a_row = l7 + ((lane >> 3) & 1) * 8;
    const int a_kb  = (lane >> 4) * 16;
    const int b_col = l7 + (lane >> 4) * 8;
    const int b_kb  = ((lane >> 3) & 1) * 16;

    float c[4][4][4];
    #pragma unroll
    for (int i = 0; i < 4; i++)
        #pragma unroll
        for (int j = 0; j < 4; j++)
            #pragma unroll
            for (int k = 0; k < 4; k++) c[i][j][k] = 0.f;

    const int nch = K >> 5;

    /* prefetch chunk 0 */
    {
        uint32_t st = smbase;
        #pragma unroll
        for (int it = 0; it < 8; it++) {
            int comp = it >> 1;
            int row = lrow + (it & 1) * 64;
            const uint16_t* src;
            int base;
            if (comp == 0)      { src = Ah; base = bm; }
            else if (comp == 1) { src = Al; base = bm; }
            else if (comp == 2) { src = Wh; base = bn; }
            else                { src = Wl; base = bn; }
            CP_ASYNC16(st + comp * COMP_BYTES + row * BSTRIDE + lseg * 16,
                       src + (size_t)(base + row) * K + lseg * 8);
        }
        CP_COMMIT();
    }

    for (int ch = 0; ch < nch; ch++) {
        if (ch + 1 < nch) {
            uint32_t st = smbase + ((ch + 1) & 1) * STAGE_BYTES;
            int kc = (ch + 1) << 5;
            #pragma unroll
            for (int it = 0; it < 8; it++) {
                int comp = it >> 1;
                int row = lrow + (it & 1) * 64;
                const uint16_t* src;
                int base;
                if (comp == 0)      { src = Ah; base = bm; }
                else if (comp == 1) { src = Al; base = bm; }
                else if (comp == 2) { src = Wh; base = bn; }
                else                { src = Wl; base = bn; }
                CP_ASYNC16(st + comp * COMP_BYTES + row * BSTRIDE + lseg * 16,
                           src + (size_t)(base + row) * K + kc + lseg * 8);
            }
            CP_COMMIT();
            CP_WAIT(1);
        } else {
            CP_WAIT(0);
        }
        __syncthreads();

        uint32_t sAh = smbase + (ch & 1) * STAGE_BYTES;
        uint32_t sWh = sAh + 2 * COMP_BYTES;

        #pragma unroll
        for (int ks = 0; ks < 2; ks++) {
            uint32_t ah[4][4], al[4][4], bh[2][4], bl[2][4];
            #pragma unroll
            for (int mt = 0; mt < 4; mt++) {
                uint32_t base = sAh + (uint32_t)(wm * 64 + mt * 16 + a_row) * BSTRIDE
                              + a_kb + ks * 32;
                ldsm4(ah[mt], base);
                ldsm4(al[mt], base + COMP_BYTES);
            }
            #pragma unroll
            for (int pr = 0; pr < 2; pr++) {
                uint32_t base = sWh + (uint32_t)(wn * 32 + pr * 16 + b_col) * BSTRIDE
                              + b_kb + ks * 32;
                ldsm4(bh[pr], base);
                ldsm4(bl[pr], base + COMP_BYTES);
            }
            #pragma unroll
            for (int mt = 0; mt < 4; mt++)
                #pragma unroll
                for (int nt = 0; nt < 4; nt++) {
                    const uint32_t* BH = &bh[nt >> 1][(nt & 1) * 2];
                    const uint32_t* BL = &bl[nt >> 1][(nt & 1) * 2];
                    mma_bf16(c[mt][nt], ah[mt], BL);
                    mma_bf16(c[mt][nt], al[mt], BH);
                    mma_bf16(c[mt][nt], ah[mt], BH);
                }
        }
        __syncthreads();
    }

    /* ---- epilogue: scale * acc + bias ---- */
    #pragma unroll
    for (int mt = 0; mt < 4; mt++) {
        int r0 = bm + wm * 64 + mt * 16 + g;
        #pragma unroll
        for (int nt = 0; nt < 4; nt++) {
            int col = bn + wn * 32 + nt * 8 + t * 2;
            float2 gv = *(const float2*)(gg + col);
            float2 bv = *(const float2*)(bb + col);
            float2 o0, o1;
            o0.x = c[mt][nt][0] * gv.x + bv.x;
            o0.y = c[mt][nt][1] * gv.y + bv.y;
            o1.x = c[mt][nt][2] * gv.x + bv.x;
            o1.y = c[mt][nt][3] * gv.y + bv.y;
            *(float2*)(C + (size_t)r0 * N + col) = o0;
            *(float2*)(C + (size_t)(r0 + 8) * N + col) = o1;
        }
    }
}

/* --------- merged hi/lo decompose of all 4 weight tensors ----------------- */
#define NW1 (QKD*DIMC)
#define NW2 (NW1 + (QKD+DIMC)*DIMC)
#define NW3 (NW2 + HID*DIMC)
#define NW4 (NW3 + DIMC*HID)
__global__ void k_dec_all(const float* __restrict__ wq, const float* __restrict__ wkv,
                          const float* __restrict__ wf1, const float* __restrict__ wf2) {
    int i = blockIdx.x * 256 + threadIdx.x;
    const float* s; uint16_t* h; uint16_t* l; int o;
    if (i < NW1)      { s = wq;  h = g_wq_h;  l = g_wq_l;  o = i; }
    else if (i < NW2) { s = wkv; h = g_wkv_h; l = g_wkv_l; o = i - NW1; }
    else if (i < NW3) { s = wf1; h = g_wf1_h; l = g_wf1_l; o = i - NW2; }
    else if (i < NW4) { s = wf2; h = g_wf2_h; l = g_wf2_l; o = i - NW3; }
    else return;
    uint16_t hh, ll;
    bf16dec(s[o], hh, ll);
    h[o] = hh; l[o] = ll;
}

/* ------------------- NCHW -> token-layout transpose (+dec) ---------------- */
__global__ void k_transpose_in(const float* __restrict__ x) {
    __shared__ float tile[32][33];
    int ny = blockIdx.z;
    int n = ny >> 6, y = ny & 63;
    int c0 = blockIdx.y * 32;
    int x0 = blockIdx.x * 32;
    int tx = threadIdx.x, ty = threadIdx.y;
    const float* src = x + (((size_t)n*DIMC + c0)*HW + y)*HW + x0;
    for (int i = ty; i < 32; i += 8)
        tile[i][tx] = src[(size_t)i*HW*HW + tx];
    __syncthreads();
    size_t tb = (size_t)(n*4096 + y*64 + x0);
    for (int i = ty; i < 32; i += 8) {
        float v = tile[tx][i];
        size_t o = (tb + i)*DIMC + c0 + tx;
        g_xt[o] = v;
        uint16_t hh, ll; bf16dec(v, hh, ll);
        g_xt_h[o] = hh; g_xt_l[o] = ll;
    }
}

/* ---------------- per-window mean of q and of k (kv[:256]) ----------------- */
__global__ void k_winmeans() {
    int np = blockIdx.x;
    int n = np >> 8, p = np & 255;
    int o = threadIdx.x;
    int yb = (p >> 4) * 4, xb = (p & 15) * 4;
    float qs = 0.f, ks = 0.f;
    #pragma unroll
    for (int tok = 0; tok < 16; tok++) {
        size_t t = (size_t)(n*4096 + (yb + (tok>>2))*64 + xb + (tok&3));
        qs += g_q[t*QKD + o];
        ks += g_kv[t*512 + o];
    }
    g_qwin[np*256 + o] = qs * (1.f/16.f);
    g_kwin[np*256 + o] = ks * (1.f/16.f);
}

/* ---------------- routing: 256 logits per window -> top-4 indices ---------- */
__global__ void k_route() {
    __shared__ float qrow[256];
    __shared__ float logit[256];
    __shared__ float rv[256];
    __shared__ int   ri[256];
    __shared__ int   chosen[NTOPK];
    int np = blockIdx.x;
    int n = np >> 8;
    int tid = threadIdx.x;
    qrow[tid] = g_qwin[np*256 + tid] * ATT_SCALE;
    __syncthreads();
    const float* kr = &g_kwin[(size_t)n*256*256 + (size_t)tid*256];
    float a = 0.f;
    #pragma unroll 8
    for (int c = 0; c < 256; c++) a += qrow[c] * kr[c];
    logit[tid] = a;
    __syncthreads();
    for (int sel = 0; sel < NTOPK; sel++) {
        bool masked = false;
        for (int s = 0; s < sel; s++) if (chosen[s] == tid) masked = true;
        rv[tid] = masked ? -INFINITY : logit[tid];
        ri[tid] = tid;
        __syncthreads();
        for (int s = 128; s > 0; s >>= 1) {
            if (tid < s) {
                float v2 = rv[tid+s]; int i2 = ri[tid+s];
                if (v2 > rv[tid] || (v2 == rv[tid] && i2 < ri[tid])) { rv[tid] = v2; ri[tid] = i2; }
            }
            __syncthreads();
        }
        if (tid == 0) { chosen[sel] = ri[0]; g_ridx[np*4 + sel] = ri[0]; }
        __syncthreads();
    }
}

/* --------- gathered attention: block per window, 2 heads per pass ---------- */
__launch_bounds__(256)
__global__ void k_attn() {
    __shared__ float q_s[16][65];
    __shared__ float k_s[64][65];
    __shared__ float v_s[64][65];
    __shared__ int   sridx[4];
    __shared__ int   stok[64];
    int np = blockIdx.x;
    int n = np >> 8, p = np & 255;
    int tid = threadIdx.x;
    if (tid < 4) sridx[tid] = g_ridx[np*4 + tid];
    __syncthreads();
    if (tid < 64) {
        int sel = tid >> 4, tok = tid & 15;
        int ps = sridx[sel];
        stok[tid] = n*4096 + ((ps>>4)*4 + (tok>>2))*64 + (ps&15)*4 + (tok&3);
    }
    __syncthreads();
    int qtok_base = n*4096 + (p>>4)*4*64 + (p&15)*4;
    int warp = tid >> 5, lane = tid & 31;
    for (int g2 = 0; g2 < 4; g2++) {
        int c0 = g2 * 64;
        for (int i = tid; i < 16*64; i += 256) {
            int tok = i >> 6, cc = i & 63;
            size_t t = (size_t)(qtok_base + (tok>>2)*64 + (tok&3));
            q_s[tok][cc] = g_q[t*256 + c0 + cc];
        }
        for (int i = tid; i < 64*64; i += 256) {
            int kt = i >> 6, cc = i & 63;
            size_t t = (size_t)stok[kt];
            k_s[kt][cc] = g_kv[t*512 + c0 + cc];
            v_s[kt][cc] = g_kv[t*512 + 256 + c0 + cc];
        }
        __syncthreads();
        int hoff  = (warp >> 2) * 32;
        int qi    = (warp & 3) * 4 + (lane >> 3);
        int kbase = (lane & 7) * 8;
        float qreg[32];
        #pragma unroll
        for (int c = 0; c < 32; c++) qreg[c] = q_s[qi][hoff + c] * ATT_SCALE;
        float sc[8];
        #pragma unroll
        for (int j = 0; j < 8; j++) {
            float a = 0.f;
            #pragma unroll
            for (int c = 0; c < 32; c++) a += qreg[c] * k_s[kbase + j][hoff + c];
            sc[j] = a;
        }
        float mx = sc[0];
        #pragma unroll
        for (int j = 1; j < 8; j++) mx = fmaxf(mx, sc[j]);
        #pragma unroll
        for (int s = 1; s < 8; s <<= 1) mx = fmaxf(mx, __shfl_xor_sync(0xffffffffu, mx, s));
        float sum = 0.f;
        #pragma unroll
        for (int j = 0; j < 8; j++) { sc[j] = expf(sc[j] - mx); sum += sc[j]; }
        #pragma unroll
        for (int s = 1; s < 8; s <<= 1) sum += __shfl_xor_sync(0xffffffffu, sum, s);
        float inv = 1.f / sum;
        float out[32];
        #pragma unroll
        for (int c = 0; c < 32; c++) out[c] = 0.f;
        #pragma unroll
        for (int j = 0; j < 8; j++) {
            float pj = sc[j] * inv;
            #pragma unroll
            for (int c = 0; c < 32; c++) out[c] += pj * v_s[kbase + j][hoff + c];
        }
        #pragma unroll
        for (int s = 1; s < 8; s <<= 1)
            #pragma unroll
            for (int c = 0; c < 32; c++) out[c] += __shfl_xor_sync(0xffffffffu, out[c], s);
        if ((lane & 7) == 0) {
            size_t t = (size_t)(qtok_base + (qi>>2)*64 + (qi&3));
            float* dst = &g_attn[t*256 + c0 + hoff];
            #pragma unroll
            for (int c = 0; c < 32; c++) dst[c] = out[c];
        }
        __syncthreads();
    }
}

/* -- LEPE 5x5 dw + residual, rolling-window: thread = (n, ch, x), 8 y-outs -- */
__global__ __launch_bounds__(256)
void k_lepe_add(const float* __restrict__ w_lepe, const float* __restrict__ b_lepe) {
    int c  = threadIdx.x;            /* 0..255 */
    int x  = blockIdx.x;             /* 0..63  */
    int zz = blockIdx.y;             /* n*8 + yblock */
    int n  = zz >> 3, yb = (zz & 7) * 8;

    float wreg[5][5];
    #pragma unroll
    for (int i = 0; i < 5; i++)
        #pragma unroll
        for (int j = 0; j < 5; j++)
            wreg[i][j] = w_lepe[c*25 + i*5 + j];
    float bias = b_lepe[c];

    const size_t nb = (size_t)n * 4096;
    float win[5][5];

    /* preload rows yb-2 .. yb+1 into win[1..4] */
    #pragma unroll
    for (int i = 0; i < 4; i++) {
        int yy = yb - 2 + i;
        #pragma unroll
        for (int j = 0; j < 5; j++) {
            int xx = x - 2 + j;
            win[i+1][j] = (yy >= 0 && yy < 64 && xx >= 0 && xx < 64)
                ? g_kv[(nb + yy*64 + xx)*512 + 256 + c] : 0.f;
        }
    }

    #pragma unroll
    for (int oy = 0; oy < 8; oy++) {
        #pragma unroll
        for (int i = 0; i < 4; i++)
            #pragma unroll
            for (int j = 0; j < 5; j++)
                win[i][j] = win[i+1][j];
        int yy = yb + 2 + oy;
        #pragma unroll
        for (int j = 0; j < 5; j++) {
            int xx = x - 2 + j;
            win[4][j] = (yy < 64 && xx >= 0 && xx < 64)
                ? g_kv[(nb + yy*64 + xx)*512 + 256 + c] : 0.f;
        }
        float acc = bias;
        #pragma unroll
        for (int i = 0; i < 5; i++)
            #pragma unroll
            for (int j = 0; j < 5; j++)
                acc += win[i][j] * wreg[i][j];
        size_t idx = (nb + (size_t)(yb + oy)*64 + x)*256 + c;
        float r = g_xt[idx] + g_attn[idx] + acc;
        g_x1[idx] = r;
        uint16_t hh, ll; bf16dec(r, hh, ll);
        g_x1_h[idx] = hh; g_x1_l[idx] = ll;
    }
}

/* -- 3x3 dw + ReLU -> hi/lo, rolling-window: thread = (n, ch, x), 8 y-outs -- */
__global__ __launch_bounds__(256)
void k_dw3relu(const float* __restrict__ w_dw, const float* __restrict__ b_dw) {
    int ch = blockIdx.x * 256 + threadIdx.x;   /* 0..1023 */
    int x  = blockIdx.y;                       /* 0..63   */
    int zz = blockIdx.z;                       /* n*8 + yblock */
    int n  = zz >> 3, yb = (zz & 7) * 8;

    float wreg[3][3];
    #pragma unroll
    for (int i = 0; i < 3; i++)
        #pragma unroll
        for (int j = 0; j < 3; j++)
            wreg[i][j] = w_dw[ch*9 + i*3 + j];
    float bias = b_dw[ch];

    const size_t nb = (size_t)n * 4096;
    float win[3][3];

    /* preload rows yb-1, yb into win[1..2] */
    #pragma unroll
    for (int i = 0; i < 2; i++) {
        int yy = yb - 1 + i;
        #pragma unroll
        for (int j = 0; j < 3; j++) {
            int xx = x - 1 + j;
            win[i+1][j] = (yy >= 0 && yy < 64 && xx >= 0 && xx < 64)
                ? g_h1[(nb + yy*64 + xx)*1024 + ch] : 0.f;
        }
    }

    #pragma unroll
    for (int oy = 0; oy < 8; oy++) {
        #pragma unroll
        for (int i = 0; i < 2; i++)
            #pragma unroll
            for (int j = 0; j < 3; j++)
                win[i][j] = win[i+1][j];
        int yy = yb + 1 + oy;
        #pragma unroll
        for (int j = 0; j < 3; j++) {
            int xx = x - 1 + j;
            win[2][j] = (yy < 64 && xx >= 0 && xx < 64)
                ? g_h1[(nb + yy*64 + xx)*1024 + ch] : 0.f;
        }
        float acc = bias;
        #pragma unroll
        for (int i = 0; i < 3; i++)
            #pragma unroll
            for (int j = 0; j < 3; j++)
                acc += win[i][j] * wreg[i][j];
        float v = fmaxf(acc, 0.f);
        size_t idx = (nb + (size_t)(yb + oy)*64 + x)*1024 + ch;
        uint16_t hh, ll; bf16dec(v, hh, ll);
        g_h1c_h[idx] = hh; g_h1c_l[idx] = ll;
    }
}

/* --------- final residual + token-layout -> NCHW transpose ----------------- */
__global__ void k_final(float* __restrict__ out) {
    __shared__ float tile[32][33];
    int ny = blockIdx.z;
    int n = ny >> 6, y = ny & 63;
    int c0 = blockIdx.y * 32, x0 = blockIdx.x * 32;
    int tx = threadIdx.x, ty = threadIdx.y;
    size_t tb = (size_t)(n*4096 + y*64 + x0);
    for (int i = ty; i < 32; i += 8) {
        size_t o = (tb + i)*256 + c0 + tx;
        tile[i][tx] = g_x1[o] + g_h2[o];
    }
    __syncthreads();
    float* dst = out + (((size_t)n*DIMC + c0)*HW + y)*HW + x0;
    for (int i = ty; i < 32; i += 8)
        dst[(size_t)i*HW*HW + tx] = tile[tx][i];
}

/* --------------------------------------------------------------------------- */
extern "C" void kernel_launch(void* const* d_in, const int* in_sizes, int n_in,
                              void* d_out, int out_size)
{
    const float* x      = (const float*)d_in[0];
    const float* wq     = (const float*)d_in[1];
    const float* gq     = (const float*)d_in[2];
    const float* bq     = (const float*)d_in[3];
    const float* wkv    = (const float*)d_in[4];
    const float* gkv    = (const float*)d_in[5];
    const float* bkv    = (const float*)d_in[6];
    const float* w_lepe = (const float*)d_in[7];
    const float* b_lepe = (const float*)d_in[8];
    const float* w_fc1  = (const float*)d_in[9];
    const float* g_fc1  = (const float*)d_in[10];
    const float* b_fc1  = (const float*)d_in[11];
    const float* w_dw   = (const float*)d_in[12];
    const float* b_dw   = (const float*)d_in[13];
    const float* w_fc2  = (const float*)d_in[14];
    const float* g_fc2  = (const float*)d_in[15];
    const float* b_fc2  = (const float*)d_in[16];
    float* out = (float*)d_out;

    float *q, *kv, *h1, *h2;
    uint16_t *xth, *xtl, *x1h, *x1l, *h1ch, *h1cl;
    uint16_t *wqh, *wql, *wkvh, *wkvl, *wf1h, *wf1l, *wf2h, *wf2l;
    cudaGetSymbolAddress((void**)&q,    g_q);
    cudaGetSymbolAddress((void**)&kv,   g_kv);
    cudaGetSymbolAddress((void**)&h1,   g_h1);
    cudaGetSymbolAddress((void**)&h2,   g_h2);
    cudaGetSymbolAddress((void**)&xth,  g_xt_h);
    cudaGetSymbolAddress((void**)&xtl,  g_xt_l);
    cudaGetSymbolAddress((void**)&x1h,  g_x1_h);
    cudaGetSymbolAddress((void**)&x1l,  g_x1_l);
    cudaGetSymbolAddress((void**)&h1ch, g_h1c_h);
    cudaGetSymbolAddress((void**)&h1cl, g_h1c_l);
    cudaGetSymbolAddress((void**)&wqh,  g_wq_h);
    cudaGetSymbolAddress((void**)&wql,  g_wq_l);
    cudaGetSymbolAddress((void**)&wkvh, g_wkv_h);
    cudaGetSymbolAddress((void**)&wkvl, g_wkv_l);
    cudaGetSymbolAddress((void**)&wf1h, g_wf1_h);
    cudaGetSymbolAddress((void**)&wf1l, g_wf1_l);
    cudaGetSymbolAddress((void**)&wf2h, g_wf2_h);
    cudaGetSymbolAddress((void**)&wf2l, g_wf2_l);

    cudaFuncSetAttribute(k_gemm_bf3, cudaFuncAttributeMaxDynamicSharedMemorySize, GEMM_SMEM);

    dim3 tblk(32, 8);
    dim3 tgrid(2, 8, NB*HW);

    k_dec_all<<<(NW4 + 255)/256, 256>>>(wq, wkv, w_fc1, w_fc2);
    k_transpose_in<<<tgrid, tblk>>>(x);

    /* q and kv projections on tensor cores (bf16x3) */
    k_gemm_bf3<<<dim3(QKD/128, NTOK/128), 256, GEMM_SMEM>>>(xth, xtl, wqh,  wql,  gq,  bq,  q,  NTOK, QKD, DIMC);
    k_gemm_bf3<<<dim3((QKD+DIMC)/128, NTOK/128), 256, GEMM_SMEM>>>(xth, xtl, wkvh, wkvl, gkv, bkv, kv, NTOK, QKD+DIMC, DIMC);

    k_winmeans<<<NB*P2, 256>>>();
    k_route<<<NB*P2, 256>>>();
    k_attn<<<NB*P2, 256>>>();
    k_lepe_add<<<dim3(HW, NB*8), 256>>>(w_lepe, b_lepe);

    /* MLP */
    k_gemm_bf3<<<dim3(HID/128, NTOK/128), 256, GEMM_SMEM>>>(x1h, x1l, wf1h, wf1l, g_fc1, b_fc1, h1, NTOK, HID, DIMC);
    k_dw3relu<<<dim3(4, HW, NB*8), 256>>>(w_dw, b_dw);
    k_gemm_bf3<<<dim3(DIMC/128, NTOK/128), 256, GEMM_SMEM>>>(h1ch, h1cl, wf2h, wf2l, g_fc2, b_fc2, h2, NTOK, DIMC, HID);

    k_final<<<tgrid, tblk>>>(out);
}